// round 9
// baseline (speedup 1.0000x reference)
#include <cuda_runtime.h>
#include <cstdint>

// Output: [B=64, SRC_XLEN=16000, D=128] fp32.
// Rows r with (r % 4000) < 1000 get x[b, r % 4000, :]; all other rows zero.
//
// Best-known structure (R3) micro-tuned:
//  - Zero path: 19200 CTAs, each fills a 20 KiB SMEM zero buffer and issues
//    ONE cp.async.bulk store. Smaller chunks -> 8 resident CTAs/SM (thread
//    cap) -> more concurrent in-flight bulk stores per SM-TMA queue.
//  - Copy path: 4000 CTAs, each thread handles TWO independent float4 of x
//    (1 LDG -> 4 STG each, streaming .cs stores). x read once per 4 writes,
//    L2-resident.

static constexpr int B = 64;
static constexpr int SRC_XLEN = 16000;
static constexpr int L = 1000;
static constexpr int SEG_STRIDE = 4000;
static constexpr int D4 = 32;                    // float4 per row
static constexpr int ROW_BYTES = 512;

// zero path
static constexpr int ZCHUNK_ROWS = 40;
static constexpr int ZCHUNK_BYTES = ZCHUNK_ROWS * ROW_BYTES;      // 20480
static constexpr int ZCHUNK_F4 = ZCHUNK_BYTES / 16;               // 1280
static constexpr int ZCHUNKS_PER_REGION = 3000 / ZCHUNK_ROWS;     // 75
static constexpr int N_ZERO_BLOCKS = B * 4 * ZCHUNKS_PER_REGION;  // 19200

// copy path: 2 float4 per thread
static constexpr int F4_PER_COPY_CTA = 512;
static constexpr int TOTAL_F4 = B * L * D4;                       // 2,048,000
static constexpr int N_COPY_BLOCKS = TOTAL_F4 / F4_PER_COPY_CTA;  // 4000

static constexpr int N_BLOCKS = N_ZERO_BLOCKS + N_COPY_BLOCKS;    // 23200
// 23200 = 800 * 29; per group of 29: lanes 0..23 zero, lanes 24..28 copy.

static constexpr int F4_PER_BATCH_IN = L * D4;                    // 32000
static constexpr int F4_PER_BATCH_OUT = SRC_XLEN * D4;            // 512000
static constexpr int F4_PER_SEG = SEG_STRIDE * D4;                // 128000
static constexpr size_t OUT_BATCH_BYTES = (size_t)SRC_XLEN * ROW_BYTES;
static constexpr size_t OUT_SEG_BYTES = (size_t)SEG_STRIDE * ROW_BYTES;

__global__ __launch_bounds__(256) void seg_zero_pad_kernel(
    const float4* __restrict__ x,   // [64, 1000, 32] float4
    float4* __restrict__ out        // [64, 16000, 32] float4
) {
    __shared__ __align__(128) float4 zbuf[ZCHUNK_F4];   // 20 KiB

    const int bid = blockIdx.x;
    const int t = threadIdx.x;
    const int grp = bid / 29;
    const int lane = bid % 29;

    if (lane < 24) {
        // ---------- zero block: fill 20 KiB once, ONE bulk store ----------
        const int zid = grp * 24 + lane;                  // 0 .. 19199
        const int region = zid / ZCHUNKS_PER_REGION;      // 0 .. 255
        const int j = zid - region * ZCHUNKS_PER_REGION;  // 0 .. 74
        const int batch = region >> 2;
        const int seg = region & 3;

        const size_t dst_off = (size_t)batch * OUT_BATCH_BYTES
                             + (size_t)seg * OUT_SEG_BYTES
                             + (size_t)L * ROW_BYTES
                             + (size_t)j * ZCHUNK_BYTES;

        const float4 z = make_float4(0.f, 0.f, 0.f, 0.f);
        #pragma unroll
        for (int i = t; i < ZCHUNK_F4; i += 256) zbuf[i] = z;
        __syncthreads();

        if (t == 0) {
            unsigned saddr;
            asm("{ .reg .u64 tmp; cvta.to.shared.u64 tmp, %1; cvt.u32.u64 %0, tmp; }"
                : "=r"(saddr) : "l"(zbuf));
            asm volatile("fence.proxy.async.shared::cta;" ::: "memory");
            unsigned long long gptr =
                (unsigned long long)__cvta_generic_to_global((char*)out + dst_off);
            asm volatile(
                "cp.async.bulk.global.shared::cta.bulk_group [%0], [%1], %2;"
                :: "l"(gptr), "r"(saddr), "r"((unsigned)ZCHUNK_BYTES) : "memory");
            asm volatile("cp.async.bulk.commit_group;" ::: "memory");
            asm volatile("cp.async.bulk.wait_group 0;" ::: "memory");
        }
    } else {
        // ---------- copy block: 2 float4 per thread, 1 load -> 4 stores ----------
        const int cid = grp * 5 + (lane - 24);            // 0 .. 3999
        const int i0 = cid * F4_PER_COPY_CTA + t;
        const int i1 = i0 + 256;

        // element 0
        {
            const int batch = i0 / F4_PER_BATCH_IN;
            const int r32 = i0 - batch * F4_PER_BATCH_IN;
            const float4 v = __ldg(&x[i0]);
            float4* dst = out + (size_t)batch * F4_PER_BATCH_OUT + r32;
            __stcs(dst, v);
            __stcs(dst + F4_PER_SEG, v);
            __stcs(dst + 2 * F4_PER_SEG, v);
            __stcs(dst + 3 * F4_PER_SEG, v);
        }
        // element 1
        {
            const int batch = i1 / F4_PER_BATCH_IN;
            const int r32 = i1 - batch * F4_PER_BATCH_IN;
            const float4 v = __ldg(&x[i1]);
            float4* dst = out + (size_t)batch * F4_PER_BATCH_OUT + r32;
            __stcs(dst, v);
            __stcs(dst + F4_PER_SEG, v);
            __stcs(dst + 2 * F4_PER_SEG, v);
            __stcs(dst + 3 * F4_PER_SEG, v);
        }
    }
}

extern "C" void kernel_launch(void* const* d_in, const int* in_sizes, int n_in,
                              void* d_out, int out_size) {
    const float4* x = (const float4*)d_in[0];
    float4* out = (float4*)d_out;
    seg_zero_pad_kernel<<<N_BLOCKS, 256>>>(x, out);
}

// round 14
// speedup vs baseline: 1.0223x; 1.0223x over previous
#include <cuda_runtime.h>
#include <cstdint>

// Output: [B=64, SRC_XLEN=16000, D=128] fp32.
// Rows r with (r % 4000) < 1000 get x[b, r % 4000, :]; all other rows zero.
//
// R3 structure (best known: 84.7us) with the zero-path per-CTA wait removed:
//  - Zero path: 12800 CTAs, each fills a 30 KiB SMEM zero buffer and issues
//    ONE cp.async.bulk store, then exits WITHOUT waiting (fire-and-forget).
//    Safety invariant: SMEM staging buffers only ever contain zeros — the
//    zero-fill is the only SMEM writer in the kernel — so a late TMA read of
//    reallocated SMEM still reads zeros. Pending stores drain by kernel end.
//  - Copy path: 8000 CTAs. Each thread: 1 LDG.128 of x, 4 STG.128 to the
//    four segment destinations (x read exactly once from DRAM).

static constexpr int B = 64;
static constexpr int SRC_XLEN = 16000;
static constexpr int L = 1000;
static constexpr int SEG_STRIDE = 4000;
static constexpr int D4 = 32;                   // float4 per row
static constexpr int ROW_BYTES = 512;

static constexpr int CHUNK_ROWS = 60;
static constexpr int CHUNK_BYTES = CHUNK_ROWS * ROW_BYTES;      // 30720
static constexpr int CHUNKS_PER_REGION = 3000 / CHUNK_ROWS;     // 50
static constexpr int N_REGIONS = B * 4;                         // 256
static constexpr int N_ZERO_BLOCKS = N_REGIONS * CHUNKS_PER_REGION;  // 12800
static constexpr int N_COPY_BLOCKS = (B * L * D4) / 256;        // 8000
static constexpr int N_BLOCKS = N_ZERO_BLOCKS + N_COPY_BLOCKS;  // 20800
// 20800 = 1600 * 13; interleave 5 copy : 8 zero per group of 13.

static constexpr int F4_PER_BATCH_OUT = SRC_XLEN * D4;          // 512000
static constexpr int F4_PER_SEG = SEG_STRIDE * D4;              // 128000

__global__ __launch_bounds__(256) void seg_zero_pad_kernel(
    const float4* __restrict__ x,   // [64, 1000, 32] float4
    float4* __restrict__ out        // [64, 16000, 32] float4
) {
    __shared__ __align__(128) float4 zbuf[CHUNK_BYTES / 16];   // 30 KiB of zeros

    const int bid = blockIdx.x;
    const int t = threadIdx.x;
    const int grp = bid / 13;
    const int lane = bid % 13;

    if (lane >= 5) {
        // ---------------- zero block: fill once, ONE fire-and-forget bulk store ----
        const int zid = grp * 8 + (lane - 5);              // 0 .. 12799
        const int region = zid / CHUNKS_PER_REGION;        // 0 .. 255
        const int j = zid - region * CHUNKS_PER_REGION;    // 0 .. 49
        const int batch = region >> 2;
        const int seg = region & 3;

        const size_t dst_off = (size_t)batch * SRC_XLEN * ROW_BYTES
                             + (size_t)(seg * SEG_STRIDE + L) * ROW_BYTES
                             + (size_t)j * CHUNK_BYTES;

        const float4 z = make_float4(0.f, 0.f, 0.f, 0.f);
        #pragma unroll
        for (int i = t; i < CHUNK_BYTES / 16; i += 256) zbuf[i] = z;
        __syncthreads();

        if (t == 0) {
            unsigned long long gptr =
                (unsigned long long)__cvta_generic_to_global((char*)out + dst_off);
            unsigned saddr;
            asm("{ .reg .u64 tmp; cvta.to.shared.u64 tmp, %1; cvt.u32.u64 %0, tmp; }"
                : "=r"(saddr) : "l"(zbuf));
            asm volatile("fence.proxy.async.shared::cta;" ::: "memory");
            asm volatile(
                "cp.async.bulk.global.shared::cta.bulk_group [%0], [%1], %2;"
                :: "l"(gptr), "r"(saddr), "r"((unsigned)CHUNK_BYTES) : "memory");
            asm volatile("cp.async.bulk.commit_group;" ::: "memory");
            // NO wait: CTA exits immediately; store drains in the background.
        }
    } else {
        // ---------------- copy block: load x once, store to 4 segments ----------------
        const int cid = grp * 5 + lane;                    // 0 .. 7999
        const int gtid = cid * 256 + t;                    // 0 .. 2,047,999
        const int d4 = gtid & 31;
        const int rowflat = gtid >> 5;                     // batch * L + r
        const int batch = rowflat / L;
        const int r = rowflat - batch * L;

        const float4 v = __ldg(&x[gtid]);
        float4* dst = out + ((size_t)batch * SRC_XLEN + r) * D4 + d4;
        #pragma unroll
        for (int s = 0; s < 4; s++) {
            dst[(size_t)s * F4_PER_SEG] = v;
        }
    }
}

extern "C" void kernel_launch(void* const* d_in, const int* in_sizes, int n_in,
                              void* d_out, int out_size) {
    const float4* x = (const float4*)d_in[0];
    float4* out = (float4*)d_out;
    seg_zero_pad_kernel<<<N_BLOCKS, 256>>>(x, out);
}